// round 8
// baseline (speedup 1.0000x reference)
#include <cuda_runtime.h>
#include <cuda_fp16.h>

// Geometry: [B=2, C=1, D=160, H=192, W=160] fp32.
#define Bsz 2
#define Dd  160
#define Hh  192
#define Ww  160
#define HW  (Hh * Ww)
#define DHW (Dd * HW)
#define NTOT (Bsz * DHW)
#define INV_V (1.0f / 729.0f)
#define EPSL 1e-6f

// WH tiling: full W rows, CHO output H-rows (+8 halo), padded row stride.
#define CHO 48
#define CHH 56          // CHO + 8
#define RSTR 168        // 4 + 160 + 4
#define NT1 640         // blockDim (160, 4)

#define CD2 20          // D-chunk for column kernels

// Half intermediates: [0]=St/SA [1]=Sp/SB [2..3]=interleaved (tc,pc) pairs
// [4]=SC.  98.3 MB static scratch.
__device__ __half g_h[5][NTOT];

__device__ __forceinline__ int clampi(int v, int lo, int hi) {
    return min(max(v, lo), hi);
}

struct F8 { float4 lo, hi; };

__device__ __forceinline__ F8 ld_half8(const __half* p) {
    uint4 u = *(const uint4*)p;
    __half2 h0 = *reinterpret_cast<__half2*>(&u.x);
    __half2 h1 = *reinterpret_cast<__half2*>(&u.y);
    __half2 h2 = *reinterpret_cast<__half2*>(&u.z);
    __half2 h3 = *reinterpret_cast<__half2*>(&u.w);
    float2 a = __half22float2(h0), b = __half22float2(h1);
    float2 c = __half22float2(h2), d = __half22float2(h3);
    F8 r;
    r.lo = make_float4(a.x, a.y, b.x, b.y);
    r.hi = make_float4(c.x, c.y, d.x, d.y);
    return r;
}

__device__ __forceinline__ void acc8(F8& s, const F8& v) {
    s.lo.x += v.lo.x; s.lo.y += v.lo.y; s.lo.z += v.lo.z; s.lo.w += v.lo.w;
    s.hi.x += v.hi.x; s.hi.y += v.hi.y; s.hi.z += v.hi.z; s.hi.w += v.hi.w;
}
__device__ __forceinline__ void accd8(F8& s, const F8& p, const F8& m) {
    s.lo.x += p.lo.x - m.lo.x; s.lo.y += p.lo.y - m.lo.y;
    s.lo.z += p.lo.z - m.lo.z; s.lo.w += p.lo.w - m.lo.w;
    s.hi.x += p.hi.x - m.hi.x; s.hi.y += p.hi.y - m.hi.y;
    s.hi.z += p.hi.z - m.hi.z; s.hi.w += p.hi.w - m.hi.w;
}

// ===========================================================================
// K1: per-plane W+H 9x9 box sums of t and p -> g_h[0], g_h[1] (fp16).
// Also zeroes the output scalar. smem: sIn[56][168] + sW[56][160] = 73472 B.
// ===========================================================================
__global__ __launch_bounds__(NT1, 3)
void k_wh2(const float* __restrict__ t, const float* __restrict__ p,
           float* __restrict__ out) {
    extern __shared__ float sm[];
    float* sIn = sm;
    float* sW  = sm + CHH * RSTR;

    const int tx = threadIdx.x, ty = threadIdx.y;
    const int tid = ty * 160 + tx;
    if (blockIdx.x == 0 && blockIdx.y == 0 && blockIdx.z == 0 && tid == 0)
        *out = 0.f;
    const int h0c = blockIdx.x * CHO;
    const long pl = (long)blockIdx.z * DHW + (long)blockIdx.y * HW;

    for (int f = 0; f < 2; ++f) {
        const float* __restrict__ src = f ? p : t;
        __half* __restrict__ dst = g_h[f];
        for (int u = tid; u < CHH * 40; u += NT1) {
            int row = u / 40, c4 = u % 40;
            int gh = clampi(h0c - 4 + row, 0, Hh - 1);
            float4 v = *(const float4*)(src + pl + (long)gh * Ww + c4 * 4);
            *(float4*)(sIn + row * RSTR + 4 + c4 * 4) = v;
        }
        if (tid < CHH * 2) {
            int row = tid >> 1, side = tid & 1;
            int gh = clampi(h0c - 4 + row, 0, Hh - 1);
            float v = src[pl + (long)gh * Ww + (side ? Ww - 1 : 0)];
            float* e = sIn + row * RSTR + (side ? 164 : 0);
            e[0] = v; e[1] = v; e[2] = v; e[3] = v;
        }
        __syncthreads();
        for (int u = tid; u < CHH * 40; u += NT1) {
            int row = u / 40, s = u % 40;
            const float* rp = sIn + row * RSTR + 4 * s;
            float4 x0 = *(const float4*)rp;
            float4 x1 = *(const float4*)(rp + 4);
            float4 x2 = *(const float4*)(rp + 8);
            float s0 = x0.x + x0.y + x0.z + x0.w + x1.x + x1.y + x1.z + x1.w + x2.x;
            float s1 = s0 - x0.x + x2.y;
            float s2 = s1 - x0.y + x2.z;
            float s3 = s2 - x0.z + x2.w;
            *(float4*)(sW + row * 160 + 4 * s) = make_float4(s0, s1, s2, s3);
        }
        __syncthreads();
        {
            const int r0 = ty * 12;
            const float* c = sW + tx;
            float s = c[(r0 + 0) * 160] + c[(r0 + 1) * 160] + c[(r0 + 2) * 160]
                    + c[(r0 + 3) * 160] + c[(r0 + 4) * 160] + c[(r0 + 5) * 160]
                    + c[(r0 + 6) * 160] + c[(r0 + 7) * 160] + c[(r0 + 8) * 160];
            __half* o = dst + pl + (long)(h0c + r0) * Ww + tx;
            o[0] = __float2half_rn(s);
#pragma unroll
            for (int k = 1; k < 12; ++k) {
                s += c[(r0 + k + 8) * 160] - c[(r0 + k - 1) * 160];
                o[(long)k * Ww] = __float2half_rn(s);
            }
        }
        __syncthreads();
    }
}

// ===========================================================================
// K2: D-axis running box sum of St,Sp -> means; fused centering.
// Thread = 8 adjacent columns (uint4 half I/O, 2x float4 fp32 reads).
// Writes INTERLEAVED (tc,pc) half2 pairs into g_h[2..3].
// grid (HW/1024, D/CD2, B) = (30, 8, 2) = 480 blocks of 128.
// ===========================================================================
__global__ __launch_bounds__(128, 4)
void k_dcenter(const float* __restrict__ t, const float* __restrict__ p) {
    const int b = blockIdx.z;
    const int hw = (blockIdx.x * 128 + threadIdx.x) * 8;
    const int d0 = blockIdx.y * CD2;
    const __half* __restrict__ St = g_h[0];
    const __half* __restrict__ Sp = g_h[1];
    __half2* __restrict__ Pair = (__half2*)g_h[2];   // [NTOT] pairs (tc,pc)
    const long base = (long)b * DHW + hw;

    F8 sa = {}, sb = {};
#pragma unroll
    for (int j = -4; j <= 4; ++j) {
        long a = base + (long)clampi(d0 + j, 0, Dd - 1) * HW;
        acc8(sa, ld_half8(St + a));
        acc8(sb, ld_half8(Sp + a));
    }
#pragma unroll 2
    for (int d = d0; d < d0 + CD2; ++d) {
        if (d > d0) {
            long ap = base + (long)min(d + 4, Dd - 1) * HW;
            long am = base + (long)max(d - 5, 0) * HW;
            accd8(sa, ld_half8(St + ap), ld_half8(St + am));
            accd8(sb, ld_half8(Sp + ap), ld_half8(Sp + am));
        }
        long a = base + (long)d * HW;
        float4 t0 = *(const float4*)(t + a);
        float4 t1 = *(const float4*)(t + a + 4);
        float4 p0 = *(const float4*)(p + a);
        float4 p1 = *(const float4*)(p + a + 4);
        __half2 q0 = __floats2half2_rn(t0.x - sa.lo.x * INV_V, p0.x - sb.lo.x * INV_V);
        __half2 q1 = __floats2half2_rn(t0.y - sa.lo.y * INV_V, p0.y - sb.lo.y * INV_V);
        __half2 q2 = __floats2half2_rn(t0.z - sa.lo.z * INV_V, p0.z - sb.lo.z * INV_V);
        __half2 q3 = __floats2half2_rn(t0.w - sa.lo.w * INV_V, p0.w - sb.lo.w * INV_V);
        __half2 q4 = __floats2half2_rn(t1.x - sa.hi.x * INV_V, p1.x - sb.hi.x * INV_V);
        __half2 q5 = __floats2half2_rn(t1.y - sa.hi.y * INV_V, p1.y - sb.hi.y * INV_V);
        __half2 q6 = __floats2half2_rn(t1.z - sa.hi.z * INV_V, p1.z - sb.hi.z * INV_V);
        __half2 q7 = __floats2half2_rn(t1.w - sa.hi.w * INV_V, p1.w - sb.hi.w * INV_V);
        uint4 u0, u1;
        u0.x = *(unsigned*)&q0; u0.y = *(unsigned*)&q1;
        u0.z = *(unsigned*)&q2; u0.w = *(unsigned*)&q3;
        u1.x = *(unsigned*)&q4; u1.y = *(unsigned*)&q5;
        u1.z = *(unsigned*)&q6; u1.w = *(unsigned*)&q7;
        *(uint4*)(Pair + a) = u0;
        *(uint4*)(Pair + a + 4) = u1;
    }
}

// ===========================================================================
// K3: per-plane W+H box sums of (tc*pc, tc^2, pc^2) from interleaved pairs.
// smem: sCt/sCp half[56][168] + sW fp32[56][160] = 73472 B.
// ===========================================================================
__global__ __launch_bounds__(NT1, 3)
void k_prodwh() {
    extern __shared__ float sm[];
    __half* sCt = (__half*)sm;
    __half* sCp = sCt + CHH * RSTR;
    float*  sW  = sm + (2 * CHH * RSTR) / 2;

    const int tx = threadIdx.x, ty = threadIdx.y;
    const int tid = ty * 160 + tx;
    const int h0c = blockIdx.x * CHO;
    const long pl = (long)blockIdx.z * DHW + (long)blockIdx.y * HW;
    const __half2* __restrict__ Pair = (const __half2*)g_h[2];

    // ---- load interleaved pairs, deinterleave into smem ----
    for (int u = tid; u < CHH * 40; u += NT1) {
        int row = u / 40, c4 = u % 40;
        int gh = clampi(h0c - 4 + row, 0, Hh - 1);
        const long a = pl + (long)gh * Ww + c4 * 4;   // 4 voxels
        uint4 uu = *(const uint4*)(Pair + a);
        __half2 q0 = *reinterpret_cast<__half2*>(&uu.x);
        __half2 q1 = *reinterpret_cast<__half2*>(&uu.y);
        __half2 q2 = *reinterpret_cast<__half2*>(&uu.z);
        __half2 q3 = *reinterpret_cast<__half2*>(&uu.w);
        __half2 t01 = __lows2half2(q0, q1),  t23 = __lows2half2(q2, q3);
        __half2 p01 = __highs2half2(q0, q1), p23 = __highs2half2(q2, q3);
        uint2 ut, up;
        ut.x = *(unsigned*)&t01; ut.y = *(unsigned*)&t23;
        up.x = *(unsigned*)&p01; up.y = *(unsigned*)&p23;
        *(uint2*)(sCt + row * RSTR + 4 + c4 * 4) = ut;
        *(uint2*)(sCp + row * RSTR + 4 + c4 * 4) = up;
    }
    if (tid < CHH * 2) {
        int row = tid >> 1, side = tid & 1;
        int gh = clampi(h0c - 4 + row, 0, Hh - 1);
        const long a = pl + (long)gh * Ww + (side ? Ww - 1 : 0);
        __half2 q = Pair[a];
        __half vt = __low2half(q), vp = __high2half(q);
        __half* e0 = sCt + row * RSTR + (side ? 164 : 0);
        __half* e1 = sCp + row * RSTR + (side ? 164 : 0);
        e0[0] = vt; e0[1] = vt; e0[2] = vt; e0[3] = vt;
        e1[0] = vp; e1[1] = vp; e1[2] = vp; e1[3] = vp;
    }
    __syncthreads();

#pragma unroll
    for (int q = 0; q < 3; ++q) {
        __half* __restrict__ dst = g_h[q == 0 ? 0 : (q == 1 ? 1 : 4)];
        for (int u = tid; u < CHH * 40; u += NT1) {
            int row = u / 40, s = u % 40;
            const __half* ra = (q == 2 ? sCp : sCt) + row * RSTR + 4 * s;
            const __half* rb = (q == 1 ? sCt : sCp) + row * RSTR + 4 * s;
            float2 a01 = __half22float2(*(const __half2*)(ra));
            float2 a23 = __half22float2(*(const __half2*)(ra + 2));
            float2 a45 = __half22float2(*(const __half2*)(ra + 4));
            float2 a67 = __half22float2(*(const __half2*)(ra + 6));
            float2 a89 = __half22float2(*(const __half2*)(ra + 8));
            float2 aAB = __half22float2(*(const __half2*)(ra + 10));
            float2 b01 = __half22float2(*(const __half2*)(rb));
            float2 b23 = __half22float2(*(const __half2*)(rb + 2));
            float2 b45 = __half22float2(*(const __half2*)(rb + 4));
            float2 b67 = __half22float2(*(const __half2*)(rb + 6));
            float2 b89 = __half22float2(*(const __half2*)(rb + 8));
            float2 bAB = __half22float2(*(const __half2*)(rb + 10));
            float v0 = a01.x * b01.x, v1 = a01.y * b01.y;
            float v2 = a23.x * b23.x, v3 = a23.y * b23.y;
            float v4 = a45.x * b45.x, v5 = a45.y * b45.y;
            float v6 = a67.x * b67.x, v7 = a67.y * b67.y;
            float v8 = a89.x * b89.x, v9 = a89.y * b89.y;
            float v10 = aAB.x * bAB.x, v11 = aAB.y * bAB.y;
            float s0 = v0 + v1 + v2 + v3 + v4 + v5 + v6 + v7 + v8;
            float s1 = s0 - v0 + v9;
            float s2 = s1 - v1 + v10;
            float s3 = s2 - v2 + v11;
            *(float4*)(sW + row * 160 + 4 * s) = make_float4(s0, s1, s2, s3);
        }
        __syncthreads();
        {
            const int r0 = ty * 12;
            const float* c = sW + tx;
            float s = c[(r0 + 0) * 160] + c[(r0 + 1) * 160] + c[(r0 + 2) * 160]
                    + c[(r0 + 3) * 160] + c[(r0 + 4) * 160] + c[(r0 + 5) * 160]
                    + c[(r0 + 6) * 160] + c[(r0 + 7) * 160] + c[(r0 + 8) * 160];
            __half* o = dst + pl + (long)(h0c + r0) * Ww + tx;
            o[0] = __float2half_rn(s);
#pragma unroll
            for (int k = 1; k < 12; ++k) {
                s += c[(r0 + k + 8) * 160] - c[(r0 + k - 1) * 160];
                o[(long)k * Ww] = __float2half_rn(s);
            }
        }
        __syncthreads();
    }
}

// ===========================================================================
// K4: D-axis running box sums of SA,SB,SC (fp16, 8 columns/thread, uint4
// loads) + cc + mean reduction. grid (30, 8, 2) = 480 blocks of 128.
// ===========================================================================
__global__ __launch_bounds__(128, 4)
void k_d3cc(float* __restrict__ out) {
    const int b = blockIdx.z;
    const int hw = (blockIdx.x * 128 + threadIdx.x) * 8;
    const int d0 = blockIdx.y * CD2;
    const __half* __restrict__ A = g_h[0];
    const __half* __restrict__ B = g_h[1];
    const __half* __restrict__ C = g_h[4];
    const long base = (long)b * DHW + hw;

    F8 sa = {}, sb = {}, sc = {};
#pragma unroll
    for (int j = -4; j <= 4; ++j) {
        long a = base + (long)clampi(d0 + j, 0, Dd - 1) * HW;
        acc8(sa, ld_half8(A + a));
        acc8(sb, ld_half8(B + a));
        acc8(sc, ld_half8(C + a));
    }
    float acc = 0.f;
#pragma unroll 2
    for (int d = d0; d < d0 + CD2; ++d) {
        if (d > d0) {
            long ap = base + (long)min(d + 4, Dd - 1) * HW;
            long am = base + (long)max(d - 5, 0) * HW;
            accd8(sa, ld_half8(A + ap), ld_half8(A + am));
            accd8(sb, ld_half8(B + ap), ld_half8(B + am));
            accd8(sc, ld_half8(C + ap), ld_half8(C + am));
        }
        acc += fminf(fmaxf(__fdividef(sa.lo.x * sa.lo.x + EPSL, sb.lo.x * sc.lo.x + EPSL), 0.f), 1.f)
             + fminf(fmaxf(__fdividef(sa.lo.y * sa.lo.y + EPSL, sb.lo.y * sc.lo.y + EPSL), 0.f), 1.f)
             + fminf(fmaxf(__fdividef(sa.lo.z * sa.lo.z + EPSL, sb.lo.z * sc.lo.z + EPSL), 0.f), 1.f)
             + fminf(fmaxf(__fdividef(sa.lo.w * sa.lo.w + EPSL, sb.lo.w * sc.lo.w + EPSL), 0.f), 1.f)
             + fminf(fmaxf(__fdividef(sa.hi.x * sa.hi.x + EPSL, sb.hi.x * sc.hi.x + EPSL), 0.f), 1.f)
             + fminf(fmaxf(__fdividef(sa.hi.y * sa.hi.y + EPSL, sb.hi.y * sc.hi.y + EPSL), 0.f), 1.f)
             + fminf(fmaxf(__fdividef(sa.hi.z * sa.hi.z + EPSL, sb.hi.z * sc.hi.z + EPSL), 0.f), 1.f)
             + fminf(fmaxf(__fdividef(sa.hi.w * sa.hi.w + EPSL, sb.hi.w * sc.hi.w + EPSL), 0.f), 1.f);
    }

    __shared__ float red[128];
    red[threadIdx.x] = acc;
    __syncthreads();
#pragma unroll
    for (int s = 64; s > 0; s >>= 1) {
        if (threadIdx.x < s) red[threadIdx.x] += red[threadIdx.x + s];
        __syncthreads();
    }
    if (threadIdx.x == 0) atomicAdd(out, -red[0] * (1.0f / (float)NTOT));
}

// ===========================================================================
extern "C" void kernel_launch(void* const* d_in, const int* in_sizes, int n_in,
                              void* d_out, int out_size) {
    const float* t = (const float*)d_in[0];  // y_true
    const float* p = (const float*)d_in[1];  // y_pred
    float* out = (float*)d_out;

    static const int SMWH = (CHH * RSTR + CHH * 160) * 4;   // 73472 B
    cudaFuncSetAttribute(k_wh2,    cudaFuncAttributeMaxDynamicSharedMemorySize, SMWH);
    cudaFuncSetAttribute(k_prodwh, cudaFuncAttributeMaxDynamicSharedMemorySize, SMWH);

    const dim3 bwh(160, 4);
    const dim3 gwh(Hh / CHO, Dd, Bsz);               // (4, 160, 2)
    const dim3 gcol(HW / 1024, Dd / CD2, Bsz);       // (30, 8, 2) = 480 blocks

    k_wh2<<<gwh, bwh, SMWH>>>(t, p, out);
    k_dcenter<<<gcol, 128>>>(t, p);
    k_prodwh<<<gwh, bwh, SMWH>>>();
    k_d3cc<<<gcol, 128>>>(out);
}

// round 9
// speedup vs baseline: 1.0275x; 1.0275x over previous
#include <cuda_runtime.h>
#include <cuda_fp16.h>

// Geometry: [B=2, C=1, D=160, H=192, W=160] fp32.
#define Bsz 2
#define Dd  160
#define Hh  192
#define Ww  160
#define HW  (Hh * Ww)
#define DHW (Dd * HW)
#define NTOT (Bsz * DHW)
#define INV_V (1.0f / 729.0f)
#define EPSL 1e-6f

// WH tiling: full W rows, CHO output H-rows (+8 halo), padded row stride.
#define CHO 48
#define CHH 56          // CHO + 8
#define RSTR 168        // 4 + 160 + 4
#define NT1 640         // blockDim (160, 4)

#define CD2 20          // D-chunk for column kernels

// Half intermediates: [0]=St/SA [1]=Sp/SB [2..3]=interleaved (tc,pc) pairs
// [4]=SC.  98.3 MB static scratch.
__device__ __half g_h[5][NTOT];

__device__ __forceinline__ int clampi(int v, int lo, int hi) {
    return min(max(v, lo), hi);
}

__device__ __forceinline__ float4 ld_half4(const __half* p) {
    uint2 u = *(const uint2*)p;
    __half2 lo = *reinterpret_cast<__half2*>(&u.x);
    __half2 hi = *reinterpret_cast<__half2*>(&u.y);
    float2 a = __half22float2(lo), b = __half22float2(hi);
    return make_float4(a.x, a.y, b.x, b.y);
}

// ===========================================================================
// K1: per-plane W+H 9x9 box sums of t and p -> g_h[0], g_h[1] (fp16).
// Also zeroes the output scalar. smem: sIn[56][168] + sW[56][160] = 73472 B.
// ===========================================================================
__global__ __launch_bounds__(NT1, 3)
void k_wh2(const float* __restrict__ t, const float* __restrict__ p,
           float* __restrict__ out) {
    extern __shared__ float sm[];
    float* sIn = sm;
    float* sW  = sm + CHH * RSTR;

    const int tx = threadIdx.x, ty = threadIdx.y;
    const int tid = ty * 160 + tx;
    if (blockIdx.x == 0 && blockIdx.y == 0 && blockIdx.z == 0 && tid == 0)
        *out = 0.f;
    const int h0c = blockIdx.x * CHO;
    const long pl = (long)blockIdx.z * DHW + (long)blockIdx.y * HW;

    for (int f = 0; f < 2; ++f) {
        const float* __restrict__ src = f ? p : t;
        __half* __restrict__ dst = g_h[f];
        for (int u = tid; u < CHH * 40; u += NT1) {
            int row = u / 40, c4 = u % 40;
            int gh = clampi(h0c - 4 + row, 0, Hh - 1);
            float4 v = *(const float4*)(src + pl + (long)gh * Ww + c4 * 4);
            *(float4*)(sIn + row * RSTR + 4 + c4 * 4) = v;
        }
        if (tid < CHH * 2) {
            int row = tid >> 1, side = tid & 1;
            int gh = clampi(h0c - 4 + row, 0, Hh - 1);
            float v = src[pl + (long)gh * Ww + (side ? Ww - 1 : 0)];
            float* e = sIn + row * RSTR + (side ? 164 : 0);
            e[0] = v; e[1] = v; e[2] = v; e[3] = v;
        }
        __syncthreads();
        for (int u = tid; u < CHH * 40; u += NT1) {
            int row = u / 40, s = u % 40;
            const float* rp = sIn + row * RSTR + 4 * s;
            float4 x0 = *(const float4*)rp;
            float4 x1 = *(const float4*)(rp + 4);
            float4 x2 = *(const float4*)(rp + 8);
            float s0 = x0.x + x0.y + x0.z + x0.w + x1.x + x1.y + x1.z + x1.w + x2.x;
            float s1 = s0 - x0.x + x2.y;
            float s2 = s1 - x0.y + x2.z;
            float s3 = s2 - x0.z + x2.w;
            *(float4*)(sW + row * 160 + 4 * s) = make_float4(s0, s1, s2, s3);
        }
        __syncthreads();
        {
            const int r0 = ty * 12;
            const float* c = sW + tx;
            float s = c[(r0 + 0) * 160] + c[(r0 + 1) * 160] + c[(r0 + 2) * 160]
                    + c[(r0 + 3) * 160] + c[(r0 + 4) * 160] + c[(r0 + 5) * 160]
                    + c[(r0 + 6) * 160] + c[(r0 + 7) * 160] + c[(r0 + 8) * 160];
            __half* o = dst + pl + (long)(h0c + r0) * Ww + tx;
            o[0] = __float2half_rn(s);
#pragma unroll
            for (int k = 1; k < 12; ++k) {
                s += c[(r0 + k + 8) * 160] - c[(r0 + k - 1) * 160];
                o[(long)k * Ww] = __float2half_rn(s);
            }
        }
        __syncthreads();
    }
}

// ===========================================================================
// K2: D-axis running box sum of St,Sp -> means; fused centering.
// Thread = 4 adjacent columns (uint2 half reads, float4 fp32 reads).
// Writes INTERLEAVED (tc,pc) half2 pairs (one uint4 per 4 voxels).
// grid (HW/512, D/CD2, B) = (60, 8, 2) = 960 blocks of 128.
// ===========================================================================
__global__ __launch_bounds__(128, 8)
void k_dcenter(const float* __restrict__ t, const float* __restrict__ p) {
    const int b = blockIdx.z;
    const int hw = (blockIdx.x * 128 + threadIdx.x) * 4;
    const int d0 = blockIdx.y * CD2;
    const __half* __restrict__ St = g_h[0];
    const __half* __restrict__ Sp = g_h[1];
    __half2* __restrict__ Pair = (__half2*)g_h[2];   // [NTOT] pairs (tc,pc)
    const long base = (long)b * DHW + hw;

    float4 sa = make_float4(0.f, 0.f, 0.f, 0.f), sb = sa;
#pragma unroll
    for (int j = -4; j <= 4; ++j) {
        long a = base + (long)clampi(d0 + j, 0, Dd - 1) * HW;
        float4 va = ld_half4(St + a);
        float4 vb = ld_half4(Sp + a);
        sa.x += va.x; sa.y += va.y; sa.z += va.z; sa.w += va.w;
        sb.x += vb.x; sb.y += vb.y; sb.z += vb.z; sb.w += vb.w;
    }
#pragma unroll 4
    for (int d = d0; d < d0 + CD2; ++d) {
        if (d > d0) {
            long ap = base + (long)min(d + 4, Dd - 1) * HW;
            long am = base + (long)max(d - 5, 0) * HW;
            float4 pa = ld_half4(St + ap), ma = ld_half4(St + am);
            float4 pb = ld_half4(Sp + ap), mb = ld_half4(Sp + am);
            sa.x += pa.x - ma.x; sa.y += pa.y - ma.y;
            sa.z += pa.z - ma.z; sa.w += pa.w - ma.w;
            sb.x += pb.x - mb.x; sb.y += pb.y - mb.y;
            sb.z += pb.z - mb.z; sb.w += pb.w - mb.w;
        }
        long a = base + (long)d * HW;
        float4 vt = *(const float4*)(t + a);
        float4 vp = *(const float4*)(p + a);
        __half2 q0 = __floats2half2_rn(vt.x - sa.x * INV_V, vp.x - sb.x * INV_V);
        __half2 q1 = __floats2half2_rn(vt.y - sa.y * INV_V, vp.y - sb.y * INV_V);
        __half2 q2 = __floats2half2_rn(vt.z - sa.z * INV_V, vp.z - sb.z * INV_V);
        __half2 q3 = __floats2half2_rn(vt.w - sa.w * INV_V, vp.w - sb.w * INV_V);
        uint4 u;
        u.x = *(unsigned*)&q0; u.y = *(unsigned*)&q1;
        u.z = *(unsigned*)&q2; u.w = *(unsigned*)&q3;
        *(uint4*)(Pair + a) = u;
    }
}

// ===========================================================================
// K3: per-plane W+H box sums of (tc*pc, tc^2, pc^2) from interleaved pairs.
// smem: sCt/sCp half[56][168] + sW fp32[56][160] = 73472 B.
// ===========================================================================
__global__ __launch_bounds__(NT1, 3)
void k_prodwh() {
    extern __shared__ float sm[];
    __half* sCt = (__half*)sm;
    __half* sCp = sCt + CHH * RSTR;
    float*  sW  = sm + (2 * CHH * RSTR) / 2;

    const int tx = threadIdx.x, ty = threadIdx.y;
    const int tid = ty * 160 + tx;
    const int h0c = blockIdx.x * CHO;
    const long pl = (long)blockIdx.z * DHW + (long)blockIdx.y * HW;
    const __half2* __restrict__ Pair = (const __half2*)g_h[2];

    // ---- load interleaved pairs, deinterleave into smem ----
    for (int u = tid; u < CHH * 40; u += NT1) {
        int row = u / 40, c4 = u % 40;
        int gh = clampi(h0c - 4 + row, 0, Hh - 1);
        const long a = pl + (long)gh * Ww + c4 * 4;   // 4 voxels
        uint4 uu = *(const uint4*)(Pair + a);
        __half2 q0 = *reinterpret_cast<__half2*>(&uu.x);
        __half2 q1 = *reinterpret_cast<__half2*>(&uu.y);
        __half2 q2 = *reinterpret_cast<__half2*>(&uu.z);
        __half2 q3 = *reinterpret_cast<__half2*>(&uu.w);
        __half2 t01 = __lows2half2(q0, q1),  t23 = __lows2half2(q2, q3);
        __half2 p01 = __highs2half2(q0, q1), p23 = __highs2half2(q2, q3);
        uint2 ut, up;
        ut.x = *(unsigned*)&t01; ut.y = *(unsigned*)&t23;
        up.x = *(unsigned*)&p01; up.y = *(unsigned*)&p23;
        *(uint2*)(sCt + row * RSTR + 4 + c4 * 4) = ut;
        *(uint2*)(sCp + row * RSTR + 4 + c4 * 4) = up;
    }
    if (tid < CHH * 2) {
        int row = tid >> 1, side = tid & 1;
        int gh = clampi(h0c - 4 + row, 0, Hh - 1);
        const long a = pl + (long)gh * Ww + (side ? Ww - 1 : 0);
        __half2 q = Pair[a];
        __half vt = __low2half(q), vp = __high2half(q);
        __half* e0 = sCt + row * RSTR + (side ? 164 : 0);
        __half* e1 = sCp + row * RSTR + (side ? 164 : 0);
        e0[0] = vt; e0[1] = vt; e0[2] = vt; e0[3] = vt;
        e1[0] = vp; e1[1] = vp; e1[2] = vp; e1[3] = vp;
    }
    __syncthreads();

#pragma unroll
    for (int q = 0; q < 3; ++q) {
        __half* __restrict__ dst = g_h[q == 0 ? 0 : (q == 1 ? 1 : 4)];
        for (int u = tid; u < CHH * 40; u += NT1) {
            int row = u / 40, s = u % 40;
            const __half* ra = (q == 2 ? sCp : sCt) + row * RSTR + 4 * s;
            const __half* rb = (q == 1 ? sCt : sCp) + row * RSTR + 4 * s;
            float2 a01 = __half22float2(*(const __half2*)(ra));
            float2 a23 = __half22float2(*(const __half2*)(ra + 2));
            float2 a45 = __half22float2(*(const __half2*)(ra + 4));
            float2 a67 = __half22float2(*(const __half2*)(ra + 6));
            float2 a89 = __half22float2(*(const __half2*)(ra + 8));
            float2 aAB = __half22float2(*(const __half2*)(ra + 10));
            float2 b01 = __half22float2(*(const __half2*)(rb));
            float2 b23 = __half22float2(*(const __half2*)(rb + 2));
            float2 b45 = __half22float2(*(const __half2*)(rb + 4));
            float2 b67 = __half22float2(*(const __half2*)(rb + 6));
            float2 b89 = __half22float2(*(const __half2*)(rb + 8));
            float2 bAB = __half22float2(*(const __half2*)(rb + 10));
            float v0 = a01.x * b01.x, v1 = a01.y * b01.y;
            float v2 = a23.x * b23.x, v3 = a23.y * b23.y;
            float v4 = a45.x * b45.x, v5 = a45.y * b45.y;
            float v6 = a67.x * b67.x, v7 = a67.y * b67.y;
            float v8 = a89.x * b89.x, v9 = a89.y * b89.y;
            float v10 = aAB.x * bAB.x, v11 = aAB.y * bAB.y;
            float s0 = v0 + v1 + v2 + v3 + v4 + v5 + v6 + v7 + v8;
            float s1 = s0 - v0 + v9;
            float s2 = s1 - v1 + v10;
            float s3 = s2 - v2 + v11;
            *(float4*)(sW + row * 160 + 4 * s) = make_float4(s0, s1, s2, s3);
        }
        __syncthreads();
        {
            const int r0 = ty * 12;
            const float* c = sW + tx;
            float s = c[(r0 + 0) * 160] + c[(r0 + 1) * 160] + c[(r0 + 2) * 160]
                    + c[(r0 + 3) * 160] + c[(r0 + 4) * 160] + c[(r0 + 5) * 160]
                    + c[(r0 + 6) * 160] + c[(r0 + 7) * 160] + c[(r0 + 8) * 160];
            __half* o = dst + pl + (long)(h0c + r0) * Ww + tx;
            o[0] = __float2half_rn(s);
#pragma unroll
            for (int k = 1; k < 12; ++k) {
                s += c[(r0 + k + 8) * 160] - c[(r0 + k - 1) * 160];
                o[(long)k * Ww] = __float2half_rn(s);
            }
        }
        __syncthreads();
    }
}

// ===========================================================================
// K4: D-axis running box sums of SA,SB,SC (fp16, 4 columns/thread) + cc +
// mean reduction. grid (60, 8, 2) = 960 blocks of 128.
// ===========================================================================
__global__ __launch_bounds__(128, 8)
void k_d3cc(float* __restrict__ out) {
    const int b = blockIdx.z;
    const int hw = (blockIdx.x * 128 + threadIdx.x) * 4;
    const int d0 = blockIdx.y * CD2;
    const __half* __restrict__ A = g_h[0];
    const __half* __restrict__ B = g_h[1];
    const __half* __restrict__ C = g_h[4];
    const long base = (long)b * DHW + hw;

    float4 sa = make_float4(0.f, 0.f, 0.f, 0.f), sb = sa, sc = sa;
#pragma unroll
    for (int j = -4; j <= 4; ++j) {
        long a = base + (long)clampi(d0 + j, 0, Dd - 1) * HW;
        float4 va = ld_half4(A + a);
        float4 vb = ld_half4(B + a);
        float4 vc = ld_half4(C + a);
        sa.x += va.x; sa.y += va.y; sa.z += va.z; sa.w += va.w;
        sb.x += vb.x; sb.y += vb.y; sb.z += vb.z; sb.w += vb.w;
        sc.x += vc.x; sc.y += vc.y; sc.z += vc.z; sc.w += vc.w;
    }
    float acc =
        fminf(fmaxf(__fdividef(sa.x * sa.x + EPSL, sb.x * sc.x + EPSL), 0.f), 1.f)
      + fminf(fmaxf(__fdividef(sa.y * sa.y + EPSL, sb.y * sc.y + EPSL), 0.f), 1.f)
      + fminf(fmaxf(__fdividef(sa.z * sa.z + EPSL, sb.z * sc.z + EPSL), 0.f), 1.f)
      + fminf(fmaxf(__fdividef(sa.w * sa.w + EPSL, sb.w * sc.w + EPSL), 0.f), 1.f);
#pragma unroll 4
    for (int d = d0 + 1; d < d0 + CD2; ++d) {
        long ap = base + (long)min(d + 4, Dd - 1) * HW;
        long am = base + (long)max(d - 5, 0) * HW;
        float4 pa = ld_half4(A + ap), ma = ld_half4(A + am);
        float4 pb = ld_half4(B + ap), mb = ld_half4(B + am);
        float4 pc = ld_half4(C + ap), mc = ld_half4(C + am);
        sa.x += pa.x - ma.x; sa.y += pa.y - ma.y;
        sa.z += pa.z - ma.z; sa.w += pa.w - ma.w;
        sb.x += pb.x - mb.x; sb.y += pb.y - mb.y;
        sb.z += pb.z - mb.z; sb.w += pb.w - mb.w;
        sc.x += pc.x - mc.x; sc.y += pc.y - mc.y;
        sc.z += pc.z - mc.z; sc.w += pc.w - mc.w;
        acc +=
            fminf(fmaxf(__fdividef(sa.x * sa.x + EPSL, sb.x * sc.x + EPSL), 0.f), 1.f)
          + fminf(fmaxf(__fdividef(sa.y * sa.y + EPSL, sb.y * sc.y + EPSL), 0.f), 1.f)
          + fminf(fmaxf(__fdividef(sa.z * sa.z + EPSL, sb.z * sc.z + EPSL), 0.f), 1.f)
          + fminf(fmaxf(__fdividef(sa.w * sa.w + EPSL, sb.w * sc.w + EPSL), 0.f), 1.f);
    }

    __shared__ float red[128];
    red[threadIdx.x] = acc;
    __syncthreads();
#pragma unroll
    for (int s = 64; s > 0; s >>= 1) {
        if (threadIdx.x < s) red[threadIdx.x] += red[threadIdx.x + s];
        __syncthreads();
    }
    if (threadIdx.x == 0) atomicAdd(out, -red[0] * (1.0f / (float)NTOT));
}

// ===========================================================================
extern "C" void kernel_launch(void* const* d_in, const int* in_sizes, int n_in,
                              void* d_out, int out_size) {
    const float* t = (const float*)d_in[0];  // y_true
    const float* p = (const float*)d_in[1];  // y_pred
    float* out = (float*)d_out;

    static const int SMWH = (CHH * RSTR + CHH * 160) * 4;   // 73472 B
    cudaFuncSetAttribute(k_wh2,    cudaFuncAttributeMaxDynamicSharedMemorySize, SMWH);
    cudaFuncSetAttribute(k_prodwh, cudaFuncAttributeMaxDynamicSharedMemorySize, SMWH);

    const dim3 bwh(160, 4);
    const dim3 gwh(Hh / CHO, Dd, Bsz);               // (4, 160, 2)
    const dim3 gcol(HW / 512, Dd / CD2, Bsz);        // (60, 8, 2) = 960 blocks

    k_wh2<<<gwh, bwh, SMWH>>>(t, p, out);
    k_dcenter<<<gcol, 128>>>(t, p);
    k_prodwh<<<gwh, bwh, SMWH>>>();
    k_d3cc<<<gcol, 128>>>(out);
}

// round 10
// speedup vs baseline: 1.0722x; 1.0435x over previous
#include <cuda_runtime.h>
#include <cuda_fp16.h>

// Geometry: [B=2, C=1, D=160, H=192, W=160] fp32.
#define Bsz 2
#define Dd  160
#define Hh  192
#define Ww  160
#define HW  (Hh * Ww)
#define DHW (Dd * HW)
#define NTOT (Bsz * DHW)
#define INV_V (1.0f / 729.0f)
#define EPSL 1e-6f

// WH tiling: full W rows, CHO output H-rows (+8 halo), padded row stride.
#define CHO 48
#define CHH 56          // CHO + 8
#define RSTR 168        // 4 + 160 + 4
#define NT1 640         // blockDim (160, 4)

#define CD2 20          // D-chunk for column kernels

// Half intermediates: [0]=St/SA [1]=Sp/SB [2..3]=interleaved (tc,pc) pairs
// [4]=SC.  98.3 MB static scratch.
__device__ __half g_h[5][NTOT];

__device__ __forceinline__ int clampi(int v, int lo, int hi) {
    return min(max(v, lo), hi);
}

__device__ __forceinline__ float4 ld_half4(const __half* p) {
    uint2 u = *(const uint2*)p;
    __half2 lo = *reinterpret_cast<__half2*>(&u.x);
    __half2 hi = *reinterpret_cast<__half2*>(&u.y);
    float2 a = __half22float2(lo), b = __half22float2(hi);
    return make_float4(a.x, a.y, b.x, b.y);
}

// ===========================================================================
// K1: per-plane W+H 9x9 box sums of t and p -> g_h[0], g_h[1] (fp16).
// Also zeroes the output scalar. smem: sIn[56][168] + sW[56][160] = 73472 B.
// ===========================================================================
__global__ __launch_bounds__(NT1, 3)
void k_wh2(const float* __restrict__ t, const float* __restrict__ p,
           float* __restrict__ out) {
    extern __shared__ float sm[];
    float* sIn = sm;
    float* sW  = sm + CHH * RSTR;

    const int tx = threadIdx.x, ty = threadIdx.y;
    const int tid = ty * 160 + tx;
    if (blockIdx.x == 0 && blockIdx.y == 0 && blockIdx.z == 0 && tid == 0)
        *out = 0.f;
    const int h0c = blockIdx.x * CHO;
    const long pl = (long)blockIdx.z * DHW + (long)blockIdx.y * HW;

    for (int f = 0; f < 2; ++f) {
        const float* __restrict__ src = f ? p : t;
        __half* __restrict__ dst = g_h[f];
        for (int u = tid; u < CHH * 40; u += NT1) {
            int row = u / 40, c4 = u % 40;
            int gh = clampi(h0c - 4 + row, 0, Hh - 1);
            float4 v = *(const float4*)(src + pl + (long)gh * Ww + c4 * 4);
            *(float4*)(sIn + row * RSTR + 4 + c4 * 4) = v;
        }
        if (tid < CHH * 2) {
            int row = tid >> 1, side = tid & 1;
            int gh = clampi(h0c - 4 + row, 0, Hh - 1);
            float v = src[pl + (long)gh * Ww + (side ? Ww - 1 : 0)];
            float* e = sIn + row * RSTR + (side ? 164 : 0);
            e[0] = v; e[1] = v; e[2] = v; e[3] = v;
        }
        __syncthreads();
        for (int u = tid; u < CHH * 40; u += NT1) {
            int row = u / 40, s = u % 40;
            const float* rp = sIn + row * RSTR + 4 * s;
            float4 x0 = *(const float4*)rp;
            float4 x1 = *(const float4*)(rp + 4);
            float4 x2 = *(const float4*)(rp + 8);
            float s0 = x0.x + x0.y + x0.z + x0.w + x1.x + x1.y + x1.z + x1.w + x2.x;
            float s1 = s0 - x0.x + x2.y;
            float s2 = s1 - x0.y + x2.z;
            float s3 = s2 - x0.z + x2.w;
            *(float4*)(sW + row * 160 + 4 * s) = make_float4(s0, s1, s2, s3);
        }
        __syncthreads();
        {
            const int r0 = ty * 12;
            const float* c = sW + tx;
            float s = c[(r0 + 0) * 160] + c[(r0 + 1) * 160] + c[(r0 + 2) * 160]
                    + c[(r0 + 3) * 160] + c[(r0 + 4) * 160] + c[(r0 + 5) * 160]
                    + c[(r0 + 6) * 160] + c[(r0 + 7) * 160] + c[(r0 + 8) * 160];
            __half* o = dst + pl + (long)(h0c + r0) * Ww + tx;
            o[0] = __float2half_rn(s);
#pragma unroll
            for (int k = 1; k < 12; ++k) {
                s += c[(r0 + k + 8) * 160] - c[(r0 + k - 1) * 160];
                o[(long)k * Ww] = __float2half_rn(s);
            }
        }
        __syncthreads();
    }
}

// ===========================================================================
// K2: D-axis running box sum of St,Sp -> means; fused centering.
// Thread = 4 adjacent columns. Peeled first plane + clean unroll-4 loop
// (R7 structure). Writes INTERLEAVED (tc,pc) half2 pairs (one uint4/4 vox).
// grid (HW/512, D/CD2, B) = (60, 8, 2) = 960 blocks of 128.
// ===========================================================================
__global__ __launch_bounds__(128, 8)
void k_dcenter(const float* __restrict__ t, const float* __restrict__ p) {
    const int b = blockIdx.z;
    const int hw = (blockIdx.x * 128 + threadIdx.x) * 4;
    const int d0 = blockIdx.y * CD2;
    const __half* __restrict__ St = g_h[0];
    const __half* __restrict__ Sp = g_h[1];
    __half2* __restrict__ Pair = (__half2*)g_h[2];   // [NTOT] pairs (tc,pc)
    const long base = (long)b * DHW + hw;

    float4 sa = make_float4(0.f, 0.f, 0.f, 0.f), sb = sa;
#pragma unroll
    for (int j = -4; j <= 4; ++j) {
        long a = base + (long)clampi(d0 + j, 0, Dd - 1) * HW;
        float4 va = ld_half4(St + a);
        float4 vb = ld_half4(Sp + a);
        sa.x += va.x; sa.y += va.y; sa.z += va.z; sa.w += va.w;
        sb.x += vb.x; sb.y += vb.y; sb.z += vb.z; sb.w += vb.w;
    }
    {   // emit plane d0
        long a = base + (long)d0 * HW;
        float4 vt = *(const float4*)(t + a);
        float4 vp = *(const float4*)(p + a);
        __half2 q0 = __floats2half2_rn(vt.x - sa.x * INV_V, vp.x - sb.x * INV_V);
        __half2 q1 = __floats2half2_rn(vt.y - sa.y * INV_V, vp.y - sb.y * INV_V);
        __half2 q2 = __floats2half2_rn(vt.z - sa.z * INV_V, vp.z - sb.z * INV_V);
        __half2 q3 = __floats2half2_rn(vt.w - sa.w * INV_V, vp.w - sb.w * INV_V);
        uint4 u;
        u.x = *(unsigned*)&q0; u.y = *(unsigned*)&q1;
        u.z = *(unsigned*)&q2; u.w = *(unsigned*)&q3;
        *(uint4*)(Pair + a) = u;
    }
#pragma unroll 4
    for (int d = d0 + 1; d < d0 + CD2; ++d) {
        long ap = base + (long)min(d + 4, Dd - 1) * HW;
        long am = base + (long)max(d - 5, 0) * HW;
        float4 pa = ld_half4(St + ap), ma = ld_half4(St + am);
        float4 pb = ld_half4(Sp + ap), mb = ld_half4(Sp + am);
        sa.x += pa.x - ma.x; sa.y += pa.y - ma.y;
        sa.z += pa.z - ma.z; sa.w += pa.w - ma.w;
        sb.x += pb.x - mb.x; sb.y += pb.y - mb.y;
        sb.z += pb.z - mb.z; sb.w += pb.w - mb.w;
        long a = base + (long)d * HW;
        float4 vt = *(const float4*)(t + a);
        float4 vp = *(const float4*)(p + a);
        __half2 q0 = __floats2half2_rn(vt.x - sa.x * INV_V, vp.x - sb.x * INV_V);
        __half2 q1 = __floats2half2_rn(vt.y - sa.y * INV_V, vp.y - sb.y * INV_V);
        __half2 q2 = __floats2half2_rn(vt.z - sa.z * INV_V, vp.z - sb.z * INV_V);
        __half2 q3 = __floats2half2_rn(vt.w - sa.w * INV_V, vp.w - sb.w * INV_V);
        uint4 u;
        u.x = *(unsigned*)&q0; u.y = *(unsigned*)&q1;
        u.z = *(unsigned*)&q2; u.w = *(unsigned*)&q3;
        *(uint4*)(Pair + a) = u;
    }
}

// ===========================================================================
// K3: per-plane W+H box sums of (tc*pc, tc^2, pc^2) from interleaved pairs.
// smem: sCt/sCp half[56][168] + sW fp32[56][160] = 73472 B.
// ===========================================================================
__global__ __launch_bounds__(NT1, 3)
void k_prodwh() {
    extern __shared__ float sm[];
    __half* sCt = (__half*)sm;
    __half* sCp = sCt + CHH * RSTR;
    float*  sW  = sm + (2 * CHH * RSTR) / 2;

    const int tx = threadIdx.x, ty = threadIdx.y;
    const int tid = ty * 160 + tx;
    const int h0c = blockIdx.x * CHO;
    const long pl = (long)blockIdx.z * DHW + (long)blockIdx.y * HW;
    const __half2* __restrict__ Pair = (const __half2*)g_h[2];

    // ---- load interleaved pairs, deinterleave into smem ----
    for (int u = tid; u < CHH * 40; u += NT1) {
        int row = u / 40, c4 = u % 40;
        int gh = clampi(h0c - 4 + row, 0, Hh - 1);
        const long a = pl + (long)gh * Ww + c4 * 4;   // 4 voxels
        uint4 uu = *(const uint4*)(Pair + a);
        __half2 q0 = *reinterpret_cast<__half2*>(&uu.x);
        __half2 q1 = *reinterpret_cast<__half2*>(&uu.y);
        __half2 q2 = *reinterpret_cast<__half2*>(&uu.z);
        __half2 q3 = *reinterpret_cast<__half2*>(&uu.w);
        __half2 t01 = __lows2half2(q0, q1),  t23 = __lows2half2(q2, q3);
        __half2 p01 = __highs2half2(q0, q1), p23 = __highs2half2(q2, q3);
        uint2 ut, up;
        ut.x = *(unsigned*)&t01; ut.y = *(unsigned*)&t23;
        up.x = *(unsigned*)&p01; up.y = *(unsigned*)&p23;
        *(uint2*)(sCt + row * RSTR + 4 + c4 * 4) = ut;
        *(uint2*)(sCp + row * RSTR + 4 + c4 * 4) = up;
    }
    if (tid < CHH * 2) {
        int row = tid >> 1, side = tid & 1;
        int gh = clampi(h0c - 4 + row, 0, Hh - 1);
        const long a = pl + (long)gh * Ww + (side ? Ww - 1 : 0);
        __half2 q = Pair[a];
        __half vt = __low2half(q), vp = __high2half(q);
        __half* e0 = sCt + row * RSTR + (side ? 164 : 0);
        __half* e1 = sCp + row * RSTR + (side ? 164 : 0);
        e0[0] = vt; e0[1] = vt; e0[2] = vt; e0[3] = vt;
        e1[0] = vp; e1[1] = vp; e1[2] = vp; e1[3] = vp;
    }
    __syncthreads();

#pragma unroll
    for (int q = 0; q < 3; ++q) {
        __half* __restrict__ dst = g_h[q == 0 ? 0 : (q == 1 ? 1 : 4)];
        for (int u = tid; u < CHH * 40; u += NT1) {
            int row = u / 40, s = u % 40;
            const __half* ra = (q == 2 ? sCp : sCt) + row * RSTR + 4 * s;
            const __half* rb = (q == 1 ? sCt : sCp) + row * RSTR + 4 * s;
            float2 a01 = __half22float2(*(const __half2*)(ra));
            float2 a23 = __half22float2(*(const __half2*)(ra + 2));
            float2 a45 = __half22float2(*(const __half2*)(ra + 4));
            float2 a67 = __half22float2(*(const __half2*)(ra + 6));
            float2 a89 = __half22float2(*(const __half2*)(ra + 8));
            float2 aAB = __half22float2(*(const __half2*)(ra + 10));
            float2 b01 = __half22float2(*(const __half2*)(rb));
            float2 b23 = __half22float2(*(const __half2*)(rb + 2));
            float2 b45 = __half22float2(*(const __half2*)(rb + 4));
            float2 b67 = __half22float2(*(const __half2*)(rb + 6));
            float2 b89 = __half22float2(*(const __half2*)(rb + 8));
            float2 bAB = __half22float2(*(const __half2*)(rb + 10));
            float v0 = a01.x * b01.x, v1 = a01.y * b01.y;
            float v2 = a23.x * b23.x, v3 = a23.y * b23.y;
            float v4 = a45.x * b45.x, v5 = a45.y * b45.y;
            float v6 = a67.x * b67.x, v7 = a67.y * b67.y;
            float v8 = a89.x * b89.x, v9 = a89.y * b89.y;
            float v10 = aAB.x * bAB.x, v11 = aAB.y * bAB.y;
            float s0 = v0 + v1 + v2 + v3 + v4 + v5 + v6 + v7 + v8;
            float s1 = s0 - v0 + v9;
            float s2 = s1 - v1 + v10;
            float s3 = s2 - v2 + v11;
            *(float4*)(sW + row * 160 + 4 * s) = make_float4(s0, s1, s2, s3);
        }
        __syncthreads();
        {
            const int r0 = ty * 12;
            const float* c = sW + tx;
            float s = c[(r0 + 0) * 160] + c[(r0 + 1) * 160] + c[(r0 + 2) * 160]
                    + c[(r0 + 3) * 160] + c[(r0 + 4) * 160] + c[(r0 + 5) * 160]
                    + c[(r0 + 6) * 160] + c[(r0 + 7) * 160] + c[(r0 + 8) * 160];
            __half* o = dst + pl + (long)(h0c + r0) * Ww + tx;
            o[0] = __float2half_rn(s);
#pragma unroll
            for (int k = 1; k < 12; ++k) {
                s += c[(r0 + k + 8) * 160] - c[(r0 + k - 1) * 160];
                o[(long)k * Ww] = __float2half_rn(s);
            }
        }
        __syncthreads();
    }
}

// ===========================================================================
// K4: D-axis running box sums of SA,SB,SC (fp16, 4 columns/thread) + cc +
// mean reduction. grid (60, 8, 2) = 960 blocks of 128.
// ===========================================================================
__global__ __launch_bounds__(128, 8)
void k_d3cc(float* __restrict__ out) {
    const int b = blockIdx.z;
    const int hw = (blockIdx.x * 128 + threadIdx.x) * 4;
    const int d0 = blockIdx.y * CD2;
    const __half* __restrict__ A = g_h[0];
    const __half* __restrict__ B = g_h[1];
    const __half* __restrict__ C = g_h[4];
    const long base = (long)b * DHW + hw;

    float4 sa = make_float4(0.f, 0.f, 0.f, 0.f), sb = sa, sc = sa;
#pragma unroll
    for (int j = -4; j <= 4; ++j) {
        long a = base + (long)clampi(d0 + j, 0, Dd - 1) * HW;
        float4 va = ld_half4(A + a);
        float4 vb = ld_half4(B + a);
        float4 vc = ld_half4(C + a);
        sa.x += va.x; sa.y += va.y; sa.z += va.z; sa.w += va.w;
        sb.x += vb.x; sb.y += vb.y; sb.z += vb.z; sb.w += vb.w;
        sc.x += vc.x; sc.y += vc.y; sc.z += vc.z; sc.w += vc.w;
    }
    float acc =
        fminf(fmaxf(__fdividef(sa.x * sa.x + EPSL, sb.x * sc.x + EPSL), 0.f), 1.f)
      + fminf(fmaxf(__fdividef(sa.y * sa.y + EPSL, sb.y * sc.y + EPSL), 0.f), 1.f)
      + fminf(fmaxf(__fdividef(sa.z * sa.z + EPSL, sb.z * sc.z + EPSL), 0.f), 1.f)
      + fminf(fmaxf(__fdividef(sa.w * sa.w + EPSL, sb.w * sc.w + EPSL), 0.f), 1.f);
#pragma unroll 4
    for (int d = d0 + 1; d < d0 + CD2; ++d) {
        long ap = base + (long)min(d + 4, Dd - 1) * HW;
        long am = base + (long)max(d - 5, 0) * HW;
        float4 pa = ld_half4(A + ap), ma = ld_half4(A + am);
        float4 pb = ld_half4(B + ap), mb = ld_half4(B + am);
        float4 pc = ld_half4(C + ap), mc = ld_half4(C + am);
        sa.x += pa.x - ma.x; sa.y += pa.y - ma.y;
        sa.z += pa.z - ma.z; sa.w += pa.w - ma.w;
        sb.x += pb.x - mb.x; sb.y += pb.y - mb.y;
        sb.z += pb.z - mb.z; sb.w += pb.w - mb.w;
        sc.x += pc.x - mc.x; sc.y += pc.y - mc.y;
        sc.z += pc.z - mc.z; sc.w += pc.w - mc.w;
        acc +=
            fminf(fmaxf(__fdividef(sa.x * sa.x + EPSL, sb.x * sc.x + EPSL), 0.f), 1.f)
          + fminf(fmaxf(__fdividef(sa.y * sa.y + EPSL, sb.y * sc.y + EPSL), 0.f), 1.f)
          + fminf(fmaxf(__fdividef(sa.z * sa.z + EPSL, sb.z * sc.z + EPSL), 0.f), 1.f)
          + fminf(fmaxf(__fdividef(sa.w * sa.w + EPSL, sb.w * sc.w + EPSL), 0.f), 1.f);
    }

    __shared__ float red[128];
    red[threadIdx.x] = acc;
    __syncthreads();
#pragma unroll
    for (int s = 64; s > 0; s >>= 1) {
        if (threadIdx.x < s) red[threadIdx.x] += red[threadIdx.x + s];
        __syncthreads();
    }
    if (threadIdx.x == 0) atomicAdd(out, -red[0] * (1.0f / (float)NTOT));
}

// ===========================================================================
extern "C" void kernel_launch(void* const* d_in, const int* in_sizes, int n_in,
                              void* d_out, int out_size) {
    const float* t = (const float*)d_in[0];  // y_true
    const float* p = (const float*)d_in[1];  // y_pred
    float* out = (float*)d_out;

    static const int SMWH = (CHH * RSTR + CHH * 160) * 4;   // 73472 B
    cudaFuncSetAttribute(k_wh2,    cudaFuncAttributeMaxDynamicSharedMemorySize, SMWH);
    cudaFuncSetAttribute(k_prodwh, cudaFuncAttributeMaxDynamicSharedMemorySize, SMWH);

    const dim3 bwh(160, 4);
    const dim3 gwh(Hh / CHO, Dd, Bsz);               // (4, 160, 2)
    const dim3 gcol(HW / 512, Dd / CD2, Bsz);        // (60, 8, 2) = 960 blocks

    k_wh2<<<gwh, bwh, SMWH>>>(t, p, out);
    k_dcenter<<<gcol, 128>>>(t, p);
    k_prodwh<<<gwh, bwh, SMWH>>>();
    k_d3cc<<<gcol, 128>>>(out);
}

// round 11
// speedup vs baseline: 1.0911x; 1.0176x over previous
#include <cuda_runtime.h>
#include <cuda_fp16.h>

// Geometry: [B=2, C=1, D=160, H=192, W=160] fp32.
#define Bsz 2
#define Dd  160
#define Hh  192
#define Ww  160
#define HW  (Hh * Ww)
#define DHW (Dd * HW)
#define NTOT (Bsz * DHW)
#define INV_V (1.0f / 729.0f)
#define EPSL 1e-6f

// WH tiling: full W rows, CHO output H-rows (+8 halo), padded row stride.
#define CHO 48
#define CHH 56          // CHO + 8
#define RSTR 168        // 4 + 160 + 4
#define NT1 640         // blockDim (160, 4)

#define CD2 20          // D-chunk for column kernels

// Half intermediates: [0]=St/SA [1]=Sp/SB [2..3]=interleaved (tc,pc) pairs
// [4]=SC.  98.3 MB static scratch.
__device__ __half g_h[5][NTOT];

__device__ __forceinline__ int clampi(int v, int lo, int hi) {
    return min(max(v, lo), hi);
}

// ===========================================================================
// K1: per-plane W+H 9x9 box sums of t and p -> g_h[0], g_h[1] (fp16).
// Also zeroes the output scalar. smem: sIn[56][168] + sW[56][160] = 73472 B.
// ===========================================================================
__global__ __launch_bounds__(NT1, 3)
void k_wh2(const float* __restrict__ t, const float* __restrict__ p,
           float* __restrict__ out) {
    extern __shared__ float sm[];
    float* sIn = sm;
    float* sW  = sm + CHH * RSTR;

    const int tx = threadIdx.x, ty = threadIdx.y;
    const int tid = ty * 160 + tx;
    if (blockIdx.x == 0 && blockIdx.y == 0 && blockIdx.z == 0 && tid == 0)
        *out = 0.f;
    const int h0c = blockIdx.x * CHO;
    const long pl = (long)blockIdx.z * DHW + (long)blockIdx.y * HW;

    for (int f = 0; f < 2; ++f) {
        const float* __restrict__ src = f ? p : t;
        __half* __restrict__ dst = g_h[f];
        for (int u = tid; u < CHH * 40; u += NT1) {
            int row = u / 40, c4 = u % 40;
            int gh = clampi(h0c - 4 + row, 0, Hh - 1);
            float4 v = *(const float4*)(src + pl + (long)gh * Ww + c4 * 4);
            *(float4*)(sIn + row * RSTR + 4 + c4 * 4) = v;
        }
        if (tid < CHH * 2) {
            int row = tid >> 1, side = tid & 1;
            int gh = clampi(h0c - 4 + row, 0, Hh - 1);
            float v = src[pl + (long)gh * Ww + (side ? Ww - 1 : 0)];
            float* e = sIn + row * RSTR + (side ? 164 : 0);
            e[0] = v; e[1] = v; e[2] = v; e[3] = v;
        }
        __syncthreads();
        for (int u = tid; u < CHH * 40; u += NT1) {
            int row = u / 40, s = u % 40;
            const float* rp = sIn + row * RSTR + 4 * s;
            float4 x0 = *(const float4*)rp;
            float4 x1 = *(const float4*)(rp + 4);
            float4 x2 = *(const float4*)(rp + 8);
            float s0 = x0.x + x0.y + x0.z + x0.w + x1.x + x1.y + x1.z + x1.w + x2.x;
            float s1 = s0 - x0.x + x2.y;
            float s2 = s1 - x0.y + x2.z;
            float s3 = s2 - x0.z + x2.w;
            *(float4*)(sW + row * 160 + 4 * s) = make_float4(s0, s1, s2, s3);
        }
        __syncthreads();
        {
            const int r0 = ty * 12;
            const float* c = sW + tx;
            float s = c[(r0 + 0) * 160] + c[(r0 + 1) * 160] + c[(r0 + 2) * 160]
                    + c[(r0 + 3) * 160] + c[(r0 + 4) * 160] + c[(r0 + 5) * 160]
                    + c[(r0 + 6) * 160] + c[(r0 + 7) * 160] + c[(r0 + 8) * 160];
            __half* o = dst + pl + (long)(h0c + r0) * Ww + tx;
            o[0] = __float2half_rn(s);
#pragma unroll
            for (int k = 1; k < 12; ++k) {
                s += c[(r0 + k + 8) * 160] - c[(r0 + k - 1) * 160];
                o[(long)k * Ww] = __float2half_rn(s);
            }
        }
        __syncthreads();
    }
}

// ===========================================================================
// K2: D-axis running box sum of St,Sp in HALF2 arithmetic -> means; fused
// centering. Thread = 4 adjacent columns; peeled first plane + unroll-4 loop.
// Writes INTERLEAVED (tc,pc) half2 pairs (one uint4 per 4 voxels).
// grid (HW/512, D/CD2, B) = (60, 8, 2) = 960 blocks of 128.
// ===========================================================================
__global__ __launch_bounds__(128, 8)
void k_dcenter(const float* __restrict__ t, const float* __restrict__ p) {
    const int b = blockIdx.z;
    const int hw = (blockIdx.x * 128 + threadIdx.x) * 4;
    const int d0 = blockIdx.y * CD2;
    const __half* __restrict__ St = g_h[0];
    const __half* __restrict__ Sp = g_h[1];
    __half2* __restrict__ Pair = (__half2*)g_h[2];   // [NTOT] pairs (tc,pc)
    const long base = (long)b * DHW + hw;

    __half2 sa0 = __float2half2_rn(0.f), sa1 = sa0, sb0 = sa0, sb1 = sa0;
#pragma unroll
    for (int j = -4; j <= 4; ++j) {
        long a = base + (long)clampi(d0 + j, 0, Dd - 1) * HW;
        uint2 ua = *(const uint2*)(St + a);
        uint2 ub = *(const uint2*)(Sp + a);
        sa0 = __hadd2(sa0, *reinterpret_cast<__half2*>(&ua.x));
        sa1 = __hadd2(sa1, *reinterpret_cast<__half2*>(&ua.y));
        sb0 = __hadd2(sb0, *reinterpret_cast<__half2*>(&ub.x));
        sb1 = __hadd2(sb1, *reinterpret_cast<__half2*>(&ub.y));
    }
    const __half2 invv = __float2half2_rn(INV_V);
    {   // emit plane d0
        long a = base + (long)d0 * HW;
        float4 vt = *(const float4*)(t + a);
        float4 vp = *(const float4*)(p + a);
        __half2 t0 = __floats2half2_rn(vt.x, vt.y), t1 = __floats2half2_rn(vt.z, vt.w);
        __half2 u0 = __floats2half2_rn(vp.x, vp.y), u1 = __floats2half2_rn(vp.z, vp.w);
        __half2 tc0 = __hsub2(t0, __hmul2(sa0, invv));
        __half2 tc1 = __hsub2(t1, __hmul2(sa1, invv));
        __half2 pc0 = __hsub2(u0, __hmul2(sb0, invv));
        __half2 pc1 = __hsub2(u1, __hmul2(sb1, invv));
        __half2 q0 = __lows2half2(tc0, pc0), q1 = __highs2half2(tc0, pc0);
        __half2 q2 = __lows2half2(tc1, pc1), q3 = __highs2half2(tc1, pc1);
        uint4 u;
        u.x = *(unsigned*)&q0; u.y = *(unsigned*)&q1;
        u.z = *(unsigned*)&q2; u.w = *(unsigned*)&q3;
        *(uint4*)(Pair + a) = u;
    }
#pragma unroll 4
    for (int d = d0 + 1; d < d0 + CD2; ++d) {
        long ap = base + (long)min(d + 4, Dd - 1) * HW;
        long am = base + (long)max(d - 5, 0) * HW;
        uint2 uap = *(const uint2*)(St + ap), uam = *(const uint2*)(St + am);
        uint2 ubp = *(const uint2*)(Sp + ap), ubm = *(const uint2*)(Sp + am);
        sa0 = __hadd2(sa0, __hsub2(*reinterpret_cast<__half2*>(&uap.x),
                                   *reinterpret_cast<__half2*>(&uam.x)));
        sa1 = __hadd2(sa1, __hsub2(*reinterpret_cast<__half2*>(&uap.y),
                                   *reinterpret_cast<__half2*>(&uam.y)));
        sb0 = __hadd2(sb0, __hsub2(*reinterpret_cast<__half2*>(&ubp.x),
                                   *reinterpret_cast<__half2*>(&ubm.x)));
        sb1 = __hadd2(sb1, __hsub2(*reinterpret_cast<__half2*>(&ubp.y),
                                   *reinterpret_cast<__half2*>(&ubm.y)));
        long a = base + (long)d * HW;
        float4 vt = *(const float4*)(t + a);
        float4 vp = *(const float4*)(p + a);
        __half2 t0 = __floats2half2_rn(vt.x, vt.y), t1 = __floats2half2_rn(vt.z, vt.w);
        __half2 u0 = __floats2half2_rn(vp.x, vp.y), u1 = __floats2half2_rn(vp.z, vp.w);
        __half2 tc0 = __hsub2(t0, __hmul2(sa0, invv));
        __half2 tc1 = __hsub2(t1, __hmul2(sa1, invv));
        __half2 pc0 = __hsub2(u0, __hmul2(sb0, invv));
        __half2 pc1 = __hsub2(u1, __hmul2(sb1, invv));
        __half2 q0 = __lows2half2(tc0, pc0), q1 = __highs2half2(tc0, pc0);
        __half2 q2 = __lows2half2(tc1, pc1), q3 = __highs2half2(tc1, pc1);
        uint4 u;
        u.x = *(unsigned*)&q0; u.y = *(unsigned*)&q1;
        u.z = *(unsigned*)&q2; u.w = *(unsigned*)&q3;
        *(uint4*)(Pair + a) = u;
    }
}

// ===========================================================================
// K3: per-plane W+H box sums of (tc*pc, tc^2, pc^2) from interleaved pairs.
// smem: sCt/sCp half[56][168] + sW fp32[56][160] = 73472 B.
// ===========================================================================
__global__ __launch_bounds__(NT1, 3)
void k_prodwh() {
    extern __shared__ float sm[];
    __half* sCt = (__half*)sm;
    __half* sCp = sCt + CHH * RSTR;
    float*  sW  = sm + (2 * CHH * RSTR) / 2;

    const int tx = threadIdx.x, ty = threadIdx.y;
    const int tid = ty * 160 + tx;
    const int h0c = blockIdx.x * CHO;
    const long pl = (long)blockIdx.z * DHW + (long)blockIdx.y * HW;
    const __half2* __restrict__ Pair = (const __half2*)g_h[2];

    // ---- load interleaved pairs, deinterleave into smem ----
    for (int u = tid; u < CHH * 40; u += NT1) {
        int row = u / 40, c4 = u % 40;
        int gh = clampi(h0c - 4 + row, 0, Hh - 1);
        const long a = pl + (long)gh * Ww + c4 * 4;   // 4 voxels
        uint4 uu = *(const uint4*)(Pair + a);
        __half2 q0 = *reinterpret_cast<__half2*>(&uu.x);
        __half2 q1 = *reinterpret_cast<__half2*>(&uu.y);
        __half2 q2 = *reinterpret_cast<__half2*>(&uu.z);
        __half2 q3 = *reinterpret_cast<__half2*>(&uu.w);
        __half2 t01 = __lows2half2(q0, q1),  t23 = __lows2half2(q2, q3);
        __half2 p01 = __highs2half2(q0, q1), p23 = __highs2half2(q2, q3);
        uint2 ut, up;
        ut.x = *(unsigned*)&t01; ut.y = *(unsigned*)&t23;
        up.x = *(unsigned*)&p01; up.y = *(unsigned*)&p23;
        *(uint2*)(sCt + row * RSTR + 4 + c4 * 4) = ut;
        *(uint2*)(sCp + row * RSTR + 4 + c4 * 4) = up;
    }
    if (tid < CHH * 2) {
        int row = tid >> 1, side = tid & 1;
        int gh = clampi(h0c - 4 + row, 0, Hh - 1);
        const long a = pl + (long)gh * Ww + (side ? Ww - 1 : 0);
        __half2 q = Pair[a];
        __half vt = __low2half(q), vp = __high2half(q);
        __half* e0 = sCt + row * RSTR + (side ? 164 : 0);
        __half* e1 = sCp + row * RSTR + (side ? 164 : 0);
        e0[0] = vt; e0[1] = vt; e0[2] = vt; e0[3] = vt;
        e1[0] = vp; e1[1] = vp; e1[2] = vp; e1[3] = vp;
    }
    __syncthreads();

#pragma unroll
    for (int q = 0; q < 3; ++q) {
        __half* __restrict__ dst = g_h[q == 0 ? 0 : (q == 1 ? 1 : 4)];
        for (int u = tid; u < CHH * 40; u += NT1) {
            int row = u / 40, s = u % 40;
            const __half* ra = (q == 2 ? sCp : sCt) + row * RSTR + 4 * s;
            const __half* rb = (q == 1 ? sCt : sCp) + row * RSTR + 4 * s;
            float2 a01 = __half22float2(*(const __half2*)(ra));
            float2 a23 = __half22float2(*(const __half2*)(ra + 2));
            float2 a45 = __half22float2(*(const __half2*)(ra + 4));
            float2 a67 = __half22float2(*(const __half2*)(ra + 6));
            float2 a89 = __half22float2(*(const __half2*)(ra + 8));
            float2 aAB = __half22float2(*(const __half2*)(ra + 10));
            float2 b01 = __half22float2(*(const __half2*)(rb));
            float2 b23 = __half22float2(*(const __half2*)(rb + 2));
            float2 b45 = __half22float2(*(const __half2*)(rb + 4));
            float2 b67 = __half22float2(*(const __half2*)(rb + 6));
            float2 b89 = __half22float2(*(const __half2*)(rb + 8));
            float2 bAB = __half22float2(*(const __half2*)(rb + 10));
            float v0 = a01.x * b01.x, v1 = a01.y * b01.y;
            float v2 = a23.x * b23.x, v3 = a23.y * b23.y;
            float v4 = a45.x * b45.x, v5 = a45.y * b45.y;
            float v6 = a67.x * b67.x, v7 = a67.y * b67.y;
            float v8 = a89.x * b89.x, v9 = a89.y * b89.y;
            float v10 = aAB.x * bAB.x, v11 = aAB.y * bAB.y;
            float s0 = v0 + v1 + v2 + v3 + v4 + v5 + v6 + v7 + v8;
            float s1 = s0 - v0 + v9;
            float s2 = s1 - v1 + v10;
            float s3 = s2 - v2 + v11;
            *(float4*)(sW + row * 160 + 4 * s) = make_float4(s0, s1, s2, s3);
        }
        __syncthreads();
        {
            const int r0 = ty * 12;
            const float* c = sW + tx;
            float s = c[(r0 + 0) * 160] + c[(r0 + 1) * 160] + c[(r0 + 2) * 160]
                    + c[(r0 + 3) * 160] + c[(r0 + 4) * 160] + c[(r0 + 5) * 160]
                    + c[(r0 + 6) * 160] + c[(r0 + 7) * 160] + c[(r0 + 8) * 160];
            __half* o = dst + pl + (long)(h0c + r0) * Ww + tx;
            o[0] = __float2half_rn(s);
#pragma unroll
            for (int k = 1; k < 12; ++k) {
                s += c[(r0 + k + 8) * 160] - c[(r0 + k - 1) * 160];
                o[(long)k * Ww] = __float2half_rn(s);
            }
        }
        __syncthreads();
    }
}

// ===========================================================================
// K4: D-axis running box sums of SA,SB,SC in HALF2 arithmetic + cc (fp32) +
// mean reduction. 4 columns/thread. grid (60, 8, 2) = 960 blocks of 128.
// ===========================================================================
__global__ __launch_bounds__(128, 8)
void k_d3cc(float* __restrict__ out) {
    const int b = blockIdx.z;
    const int hw = (blockIdx.x * 128 + threadIdx.x) * 4;
    const int d0 = blockIdx.y * CD2;
    const __half* __restrict__ A = g_h[0];
    const __half* __restrict__ B = g_h[1];
    const __half* __restrict__ C = g_h[4];
    const long base = (long)b * DHW + hw;

    __half2 sa0 = __float2half2_rn(0.f), sa1 = sa0;
    __half2 sb0 = sa0, sb1 = sa0, sc0 = sa0, sc1 = sa0;
#pragma unroll
    for (int j = -4; j <= 4; ++j) {
        long a = base + (long)clampi(d0 + j, 0, Dd - 1) * HW;
        uint2 ua = *(const uint2*)(A + a);
        uint2 ub = *(const uint2*)(B + a);
        uint2 uc = *(const uint2*)(C + a);
        sa0 = __hadd2(sa0, *reinterpret_cast<__half2*>(&ua.x));
        sa1 = __hadd2(sa1, *reinterpret_cast<__half2*>(&ua.y));
        sb0 = __hadd2(sb0, *reinterpret_cast<__half2*>(&ub.x));
        sb1 = __hadd2(sb1, *reinterpret_cast<__half2*>(&ub.y));
        sc0 = __hadd2(sc0, *reinterpret_cast<__half2*>(&uc.x));
        sc1 = __hadd2(sc1, *reinterpret_cast<__half2*>(&uc.y));
    }
    float acc;
    {
        float2 fa0 = __half22float2(sa0), fa1 = __half22float2(sa1);
        float2 fb0 = __half22float2(sb0), fb1 = __half22float2(sb1);
        float2 fc0 = __half22float2(sc0), fc1 = __half22float2(sc1);
        acc = fminf(fmaxf(__fdividef(fa0.x * fa0.x + EPSL, fb0.x * fc0.x + EPSL), 0.f), 1.f)
            + fminf(fmaxf(__fdividef(fa0.y * fa0.y + EPSL, fb0.y * fc0.y + EPSL), 0.f), 1.f)
            + fminf(fmaxf(__fdividef(fa1.x * fa1.x + EPSL, fb1.x * fc1.x + EPSL), 0.f), 1.f)
            + fminf(fmaxf(__fdividef(fa1.y * fa1.y + EPSL, fb1.y * fc1.y + EPSL), 0.f), 1.f);
    }
#pragma unroll 4
    for (int d = d0 + 1; d < d0 + CD2; ++d) {
        long ap = base + (long)min(d + 4, Dd - 1) * HW;
        long am = base + (long)max(d - 5, 0) * HW;
        uint2 uap = *(const uint2*)(A + ap), uam = *(const uint2*)(A + am);
        uint2 ubp = *(const uint2*)(B + ap), ubm = *(const uint2*)(B + am);
        uint2 ucp = *(const uint2*)(C + ap), ucm = *(const uint2*)(C + am);
        sa0 = __hadd2(sa0, __hsub2(*reinterpret_cast<__half2*>(&uap.x),
                                   *reinterpret_cast<__half2*>(&uam.x)));
        sa1 = __hadd2(sa1, __hsub2(*reinterpret_cast<__half2*>(&uap.y),
                                   *reinterpret_cast<__half2*>(&uam.y)));
        sb0 = __hadd2(sb0, __hsub2(*reinterpret_cast<__half2*>(&ubp.x),
                                   *reinterpret_cast<__half2*>(&ubm.x)));
        sb1 = __hadd2(sb1, __hsub2(*reinterpret_cast<__half2*>(&ubp.y),
                                   *reinterpret_cast<__half2*>(&ubm.y)));
        sc0 = __hadd2(sc0, __hsub2(*reinterpret_cast<__half2*>(&ucp.x),
                                   *reinterpret_cast<__half2*>(&ucm.x)));
        sc1 = __hadd2(sc1, __hsub2(*reinterpret_cast<__half2*>(&ucp.y),
                                   *reinterpret_cast<__half2*>(&ucm.y)));
        float2 fa0 = __half22float2(sa0), fa1 = __half22float2(sa1);
        float2 fb0 = __half22float2(sb0), fb1 = __half22float2(sb1);
        float2 fc0 = __half22float2(sc0), fc1 = __half22float2(sc1);
        acc += fminf(fmaxf(__fdividef(fa0.x * fa0.x + EPSL, fb0.x * fc0.x + EPSL), 0.f), 1.f)
             + fminf(fmaxf(__fdividef(fa0.y * fa0.y + EPSL, fb0.y * fc0.y + EPSL), 0.f), 1.f)
             + fminf(fmaxf(__fdividef(fa1.x * fa1.x + EPSL, fb1.x * fc1.x + EPSL), 0.f), 1.f)
             + fminf(fmaxf(__fdividef(fa1.y * fa1.y + EPSL, fb1.y * fc1.y + EPSL), 0.f), 1.f);
    }

    __shared__ float red[128];
    red[threadIdx.x] = acc;
    __syncthreads();
#pragma unroll
    for (int s = 64; s > 0; s >>= 1) {
        if (threadIdx.x < s) red[threadIdx.x] += red[threadIdx.x + s];
        __syncthreads();
    }
    if (threadIdx.x == 0) atomicAdd(out, -red[0] * (1.0f / (float)NTOT));
}

// ===========================================================================
extern "C" void kernel_launch(void* const* d_in, const int* in_sizes, int n_in,
                              void* d_out, int out_size) {
    const float* t = (const float*)d_in[0];  // y_true
    const float* p = (const float*)d_in[1];  // y_pred
    float* out = (float*)d_out;

    static const int SMWH = (CHH * RSTR + CHH * 160) * 4;   // 73472 B
    cudaFuncSetAttribute(k_wh2,    cudaFuncAttributeMaxDynamicSharedMemorySize, SMWH);
    cudaFuncSetAttribute(k_prodwh, cudaFuncAttributeMaxDynamicSharedMemorySize, SMWH);

    const dim3 bwh(160, 4);
    const dim3 gwh(Hh / CHO, Dd, Bsz);               // (4, 160, 2)
    const dim3 gcol(HW / 512, Dd / CD2, Bsz);        // (60, 8, 2) = 960 blocks

    k_wh2<<<gwh, bwh, SMWH>>>(t, p, out);
    k_dcenter<<<gcol, 128>>>(t, p);
    k_prodwh<<<gwh, bwh, SMWH>>>();
    k_d3cc<<<gcol, 128>>>(out);
}